// round 2
// baseline (speedup 1.0000x reference)
#include <cuda_runtime.h>

// Problem constants
#define BB 16
#define SS 64
#define TT_ 4096
#define CC 512
#define HH 8
#define DD 64

// Scratch (device globals: allocation-free rule)
__device__ float g_w[HH * CC];                      // folded query-side weights
__device__ float g_cb[CC];                          // bp + Wp @ bv
__device__ float g_att[BB * HH * TT_];              // 2 MB logits
__device__ float g_m[(size_t)BB * SS * HH * CC];    // 16 MB softmax-weighted eh sums
__device__ float g_tmp[BB * SS * CC];               // 2 MB per-head V-projected

__device__ __forceinline__ float warp_red_max(float v) {
#pragma unroll
    for (int o = 16; o; o >>= 1) v = fmaxf(v, __shfl_xor_sync(0xffffffffu, v, o));
    return v;
}
__device__ __forceinline__ float warp_red_sum(float v) {
#pragma unroll
    for (int o = 16; o; o >>= 1) v += __shfl_xor_sync(0xffffffffu, v, o);
    return v;
}

// ---------------------------------------------------------------------------
// Setup: q = Wq@x + bq ; w[h,c] = (1/8) * sum_d q[h*64+d] * Wk[h*64+d, c]
//        cb = bp + Wp @ bv        (bk cancels in softmax; bv commutes to cb)
// One block, 512 threads.
// ---------------------------------------------------------------------------
__global__ void setup_kernel(const float* __restrict__ x, const float* __restrict__ Wq,
                             const float* __restrict__ bq, const float* __restrict__ Wk,
                             const float* __restrict__ Wp, const float* __restrict__ bv,
                             const float* __restrict__ bp) {
    __shared__ float xs[CC], bvs[CC], qs[CC];
    int tid = threadIdx.x, lane = tid & 31, wid = tid >> 5;  // 16 warps
    xs[tid] = x[tid];
    bvs[tid] = bv[tid];
    __syncthreads();

    // warp-per-row matvecs (coalesced along c)
    for (int o = wid; o < CC; o += 16) {
        const float* r = Wq + (size_t)o * CC;
        float s = 0.f;
        for (int c = lane; c < CC; c += 32) s += r[c] * xs[c];
        s = warp_red_sum(s);
        if (lane == 0) qs[o] = s + bq[o];
    }
    for (int o = wid; o < CC; o += 16) {
        const float* r = Wp + (size_t)o * CC;
        float s = 0.f;
        for (int c = lane; c < CC; c += 32) s += r[c] * bvs[c];
        s = warp_red_sum(s);
        if (lane == 0) g_cb[o] = s + bp[o];
    }
    __syncthreads();

    const float scale = 0.125f;  // 1/sqrt(64)
    for (int idx = tid; idx < HH * CC; idx += 512) {
        int h = idx >> 9, c = idx & 511;
        float s = 0.f;
#pragma unroll 8
        for (int d = 0; d < DD; d++) s += qs[h * DD + d] * Wk[(size_t)(h * DD + d) * CC + c];
        g_w[idx] = scale * s;
    }
}

// ---------------------------------------------------------------------------
// att[b,h,t] = w[h,:] . eh[b,:,t]   (memory bound: one full eh read)
// grid (T/256, B), 256 threads, thread owns one t.
// ---------------------------------------------------------------------------
__global__ void att_kernel(const float* __restrict__ eh) {
    __shared__ float ws[HH * CC];
    int tid = threadIdx.x;
    for (int i = tid; i < HH * CC; i += 256) ws[i] = g_w[i];
    __syncthreads();

    int b = blockIdx.y;
    int t = blockIdx.x * 256 + tid;
    const float* e = eh + (size_t)b * CC * TT_ + t;
    float acc[HH];
#pragma unroll
    for (int h = 0; h < HH; h++) acc[h] = 0.f;

#pragma unroll 8
    for (int c = 0; c < CC; c++) {
        float v = e[(size_t)c * TT_];
#pragma unroll
        for (int h = 0; h < HH; h++) acc[h] = fmaf(ws[h * CC + c], v, acc[h]);
    }
    float* ao = g_att + (size_t)b * HH * TT_ + t;
#pragma unroll
    for (int h = 0; h < HH; h++) ao[(size_t)h * TT_] = acc[h];
}

// ---------------------------------------------------------------------------
// Per (b,s): softmax stats over segment, then m[h,c] = sum_t p[h,t]*eh[c,t].
// Second full eh read. t staged 16-wide through a padded shared transpose so
// each thread owns channels c=tid, tid+256 with register accumulators.
// grid (B*S), 256 threads.
// ---------------------------------------------------------------------------
#define SEG_TT 16
__global__ void seg_kernel(const float* __restrict__ eh, const int* __restrict__ ss,
                           const int* __restrict__ se) {
    __shared__ float tile[CC][SEG_TT + 1];  // 34.8 KB, conflict-free transpose
    __shared__ float ps[HH][SEG_TT];
    __shared__ float smax[HH], sinv[HH];
    __shared__ float wred[8][HH];

    int bid = blockIdx.x;
    int b = bid >> 6;
    int st = ss[bid], en = se[bid];  // en > st guaranteed
    int tid = threadIdx.x, lane = tid & 31, wid = tid >> 5;
    const float* ebase = eh + (size_t)b * CC * TT_;
    const float* abase = g_att + (size_t)b * HH * TT_;

    // phase 1: per-head max over [st, en)
    float mx[HH];
#pragma unroll
    for (int h = 0; h < HH; h++) mx[h] = -3.0e38f;
    for (int t = st + tid; t < en; t += 256) {
#pragma unroll
        for (int h = 0; h < HH; h++) mx[h] = fmaxf(mx[h], abase[(size_t)h * TT_ + t]);
    }
#pragma unroll
    for (int h = 0; h < HH; h++) mx[h] = warp_red_max(mx[h]);
    if (lane == 0) {
        for (int h = 0; h < HH; h++) wred[wid][h] = mx[h];
    }
    __syncthreads();
    if (tid < HH) {
        float v = wred[0][tid];
        for (int w = 1; w < 8; w++) v = fmaxf(v, wred[w][tid]);
        smax[tid] = v;
    }
    __syncthreads();

    // phase 2: per-head sum of exp
    float sm[HH];
#pragma unroll
    for (int h = 0; h < HH; h++) sm[h] = 0.f;
    for (int t = st + tid; t < en; t += 256) {
#pragma unroll
        for (int h = 0; h < HH; h++) sm[h] += __expf(abase[(size_t)h * TT_ + t] - smax[h]);
    }
#pragma unroll
    for (int h = 0; h < HH; h++) sm[h] = warp_red_sum(sm[h]);
    if (lane == 0) {
        for (int h = 0; h < HH; h++) wred[wid][h] = sm[h];
    }
    __syncthreads();
    if (tid < HH) {
        float v = 0.f;
        for (int w = 0; w < 8; w++) v += wred[w][tid];
        sinv[tid] = 1.f / v;  // >= 1, safe
    }
    __syncthreads();

    // phase 3: weighted accumulation; thread owns c = tid and tid+256
    float acc0[HH], acc1[HH];
#pragma unroll
    for (int h = 0; h < HH; h++) { acc0[h] = 0.f; acc1[h] = 0.f; }

    for (int t0 = st & ~(SEG_TT - 1); t0 < en; t0 += SEG_TT) {
        __syncthreads();  // previous chunk's compute done before overwrite
        if (tid < HH * SEG_TT) {
            int h = tid >> 4, j = tid & 15;
            int t = t0 + j;
            ps[h][j] = (t >= st && t < en)
                           ? __expf(abase[(size_t)h * TT_ + t] - smax[h]) * sinv[h]
                           : 0.f;
        }
#pragma unroll
        for (int i = 0; i < 32; i++) {
            int idx = tid + i * 256;
            int c = idx >> 4, j = idx & 15;
            int t = t0 + j;
            tile[c][j] = (t < en) ? ebase[(size_t)c * TT_ + t] : 0.f;
        }
        __syncthreads();
#pragma unroll 4
        for (int j = 0; j < SEG_TT; j++) {
            float e0 = tile[tid][j];
            float e1 = tile[tid + 256][j];
#pragma unroll
            for (int h = 0; h < HH; h++) {
                float p = ps[h][j];
                acc0[h] = fmaf(p, e0, acc0[h]);
                acc1[h] = fmaf(p, e1, acc1[h]);
            }
        }
    }

    float* mo = g_m + (size_t)bid * HH * CC;
#pragma unroll
    for (int h = 0; h < HH; h++) {
        mo[h * CC + tid] = acc0[h];
        mo[h * CC + tid + 256] = acc1[h];
    }
}

// ---------------------------------------------------------------------------
// fp32 tiled GEMM: C[m,n] (+= bias[n]) = sum_k A[m,k] * B[n,k]
// 64x64 tile, K-chunk 32, 256 threads, 4x4 microtile, smem stored [k][mn]
// so inner loop uses two LDS.128 + 16 FFMA per k.
// ---------------------------------------------------------------------------
__device__ __forceinline__ void gemm_body(const float* __restrict__ A,
                                          const float* __restrict__ Bm,
                                          float* __restrict__ Cm,
                                          const float* __restrict__ bias,
                                          int lda, int ldb, int ldc, int K) {
    __shared__ float As[32][68];  // 68*4=272B rows keep float4 alignment
    __shared__ float Bs[32][68];
    int tid = threadIdx.x;
    int tx = tid & 15, ty = tid >> 4;
    int m0 = blockIdx.x * 64, n0 = blockIdx.y * 64;
    float acc[4][4];
#pragma unroll
    for (int i = 0; i < 4; i++)
#pragma unroll
        for (int j = 0; j < 4; j++) acc[i][j] = 0.f;

    for (int k0 = 0; k0 < K; k0 += 32) {
#pragma unroll
        for (int i = 0; i < 8; i++) {
            int idx = tid + i * 256;      // 0..2047
            int row = idx >> 5, col = idx & 31;
            As[col][row] = A[(size_t)(m0 + row) * lda + k0 + col];
            Bs[col][row] = Bm[(size_t)(n0 + row) * ldb + k0 + col];
        }
        __syncthreads();
#pragma unroll
        for (int kk = 0; kk < 32; kk++) {
            float4 a4 = *(const float4*)&As[kk][ty * 4];
            float4 b4 = *(const float4*)&Bs[kk][tx * 4];
            float a[4] = {a4.x, a4.y, a4.z, a4.w};
            float bb[4] = {b4.x, b4.y, b4.z, b4.w};
#pragma unroll
            for (int i = 0; i < 4; i++)
#pragma unroll
                for (int j = 0; j < 4; j++) acc[i][j] = fmaf(a[i], bb[j], acc[i][j]);
        }
        __syncthreads();
    }
#pragma unroll
    for (int i = 0; i < 4; i++) {
        int mm = m0 + ty * 4 + i;
#pragma unroll
        for (int j = 0; j < 4; j++) {
            int nn = n0 + tx * 4 + j;
            float v = acc[i][j];
            if (bias) v += bias[nn];
            Cm[(size_t)mm * ldc + nn] = v;
        }
    }
}

// D1: tmp[r, h*64+d] = sum_c m[r,h,c] * Wv[h*64+d, c]   (grid 16 x 1 x 8)
__global__ void gemm1_kernel(const float* __restrict__ Wv) {
    int h = blockIdx.z;
    gemm_body(g_m + h * CC, Wv + (size_t)h * DD * CC, g_tmp + h * DD,
              nullptr, HH * CC, CC, CC, CC);
}

// D2: y[r,o] = sum_i tmp[r,i] * Wp[o,i] + cb[o]          (grid 16 x 8)
__global__ void gemm2_kernel(const float* __restrict__ Wp, float* __restrict__ out) {
    gemm_body(g_tmp, Wp, out, g_cb, CC, CC, CC, CC);
}

// ---------------------------------------------------------------------------
extern "C" void kernel_launch(void* const* d_in, const int* in_sizes, int n_in,
                              void* d_out, int out_size) {
    const float* x  = (const float*)d_in[0];
    const float* eh = (const float*)d_in[1];
    const int*   st = (const int*)d_in[2];
    const int*   en = (const int*)d_in[3];
    const float* Wq = (const float*)d_in[4];
    const float* bq = (const float*)d_in[5];
    const float* Wk = (const float*)d_in[6];
    /* d_in[7] = bk: per-head constant in logits, cancels in softmax */
    const float* Wv = (const float*)d_in[8];
    const float* bv = (const float*)d_in[9];
    const float* Wp = (const float*)d_in[10];
    const float* bp = (const float*)d_in[11];
    float* out = (float*)d_out;

    setup_kernel<<<1, 512>>>(x, Wq, bq, Wk, Wp, bv, bp);
    att_kernel<<<dim3(TT_ / 256, BB), 256>>>(eh);
    seg_kernel<<<BB * SS, 256>>>(eh, st, en);
    gemm1_kernel<<<dim3(BB * SS / 64, 1, HH), 256>>>(Wv);
    gemm2_kernel<<<dim3(BB * SS / 64, CC / 64, 1), 256>>>(Wp, out);
}